// round 12
// baseline (speedup 1.0000x reference)
#include <cuda_runtime.h>
#include <cstdint>
#include <cstddef>

// Problem constants
#define BATCH  32
#define SEQ    1024
#define INDIM  128
#define HID    512
#define LAYERS 3

// Wavefront decomposition: 3 layers x 4 batch-groups (8 batches) x 8 j-CTAs = 96 CTAs
#define NGRP 4
#define NB   8     // batches per group
#define GJ   8     // j-split (64 output columns per CTA)

// ---------------- device scratch (allocation-free rule) ------------------------
__device__ float g_P[(size_t)BATCH * SEQ * HID];              // layer-0 pre-activations
__device__ float g_hring[LAYERS][4][BATCH][HID];              // 4-slot h ring per layer
__device__ int   g_flag[LAYERS * NGRP * GJ];                  // monotonic step flags

// ---------------- PTX helpers --------------------------------------------------
__device__ __forceinline__ unsigned long long pack2(float x, float y) {
    unsigned long long r;
    asm("mov.b64 %0, {%1, %2};" : "=l"(r) : "f"(x), "f"(y));
    return r;
}
__device__ __forceinline__ unsigned long long ffma2(unsigned long long a,
                                                    unsigned long long b,
                                                    unsigned long long c) {
    unsigned long long d;
    asm("fma.rn.f32x2 %0, %1, %2, %3;" : "=l"(d) : "l"(a), "l"(b), "l"(c));
    return d;
}
__device__ __forceinline__ float pairsum(unsigned long long p) {
    unsigned lo, hi;
    asm("mov.b64 {%0, %1}, %2;" : "=r"(lo), "=r"(hi) : "l"(p));
    return __uint_as_float(lo) + __uint_as_float(hi);
}
__device__ __forceinline__ int ld_acquire_gpu(const int* p) {
    int v;
    asm volatile("ld.global.acquire.gpu.b32 %0, [%1];" : "=r"(v) : "l"(p));
    return v;
}
__device__ __forceinline__ void st_relaxed_gpu(int* p, int v) {
    asm volatile("st.global.relaxed.gpu.b32 [%0], %1;" :: "l"(p), "r"(v));
}
__device__ __forceinline__ float ldg_nc_f32(const float* p) {
    float v;
    asm volatile("ld.global.nc.f32 %0, [%1];" : "=f"(v) : "l"(p));
    return v;
}
// Immutable weights: non-coherent path is safe.
__device__ __forceinline__ ulonglong2 ldg_nc_u64x2(const float* p) {
    ulonglong2 v;
    asm volatile("ld.global.nc.v2.u64 {%0, %1}, [%2];"
                 : "=l"(v.x), "=l"(v.y) : "l"(p));
    return v;
}
// Ring data written this launch: plain (coherent) load, NOT .nc.
__device__ __forceinline__ float4 ldg_f32x4(const float* p) {
    float4 v;
    asm volatile("ld.global.v4.f32 {%0, %1, %2, %3}, [%4];"
                 : "=f"(v.x), "=f"(v.y), "=f"(v.z), "=f"(v.w) : "l"(p));
    return v;
}

// ==============================================================================
// Projection GEMM for layer 0 only:  g_P[r][n] = sum_k x[r][k] * W[n][k] + b[n]
// M=32768, K=128, N=512. 128x128 tile, BK=8, 256 threads, 8x8 microtile.
// Block (0,0) also resets the wavefront flags (stream order precedes wave_kernel).
// ==============================================================================
__global__ __launch_bounds__(256) void proj_kernel(
    const float* __restrict__ A,
    const float* __restrict__ W,
    const float* __restrict__ bias,
    int K)
{
    __shared__ float As[8][128];
    __shared__ float Bs[8][128];

    int tid = threadIdx.x;
    if (blockIdx.x == 0 && blockIdx.y == 0 && tid < LAYERS * NGRP * GJ)
        g_flag[tid] = 0;

    int m0 = blockIdx.y * 128;
    int n0 = blockIdx.x * 128;

    int lr = tid >> 1;
    int lk = (tid & 1) * 4;

    const float4* Aload = (const float4*)(A + (size_t)(m0 + lr) * K + lk);
    const float4* Wload = (const float4*)(W + (size_t)(n0 + lr) * K + lk);

    int tm = tid >> 4;
    int tn = tid & 15;

    float acc[8][8];
    #pragma unroll
    for (int i = 0; i < 8; i++)
        #pragma unroll
        for (int j = 0; j < 8; j++) acc[i][j] = 0.f;

    for (int k0 = 0; k0 < K; k0 += 8) {
        float4 av = Aload[k0 >> 2];
        float4 wv = Wload[k0 >> 2];
        As[lk + 0][lr] = av.x; As[lk + 1][lr] = av.y;
        As[lk + 2][lr] = av.z; As[lk + 3][lr] = av.w;
        Bs[lk + 0][lr] = wv.x; Bs[lk + 1][lr] = wv.y;
        Bs[lk + 2][lr] = wv.z; Bs[lk + 3][lr] = wv.w;
        __syncthreads();

        #pragma unroll
        for (int kk = 0; kk < 8; kk++) {
            float a[8], b[8];
            *(float4*)(a)     = *(const float4*)(&As[kk][tm * 8]);
            *(float4*)(a + 4) = *(const float4*)(&As[kk][tm * 8 + 4]);
            *(float4*)(b)     = *(const float4*)(&Bs[kk][tn * 8]);
            *(float4*)(b + 4) = *(const float4*)(&Bs[kk][tn * 8 + 4]);
            #pragma unroll
            for (int i = 0; i < 8; i++)
                #pragma unroll
                for (int j = 0; j < 8; j++)
                    acc[i][j] += a[i] * b[j];
        }
        __syncthreads();
    }

    float bv[8];
    #pragma unroll
    for (int j = 0; j < 8; j++) bv[j] = bias[n0 + tn * 8 + j];

    #pragma unroll
    for (int i = 0; i < 8; i++) {
        float* crow = g_P + (size_t)(m0 + tm * 8 + i) * HID + n0 + tn * 8;
        float4 v0 = make_float4(acc[i][0] + bv[0], acc[i][1] + bv[1],
                                acc[i][2] + bv[2], acc[i][3] + bv[3]);
        float4 v1 = make_float4(acc[i][4] + bv[4], acc[i][5] + bv[5],
                                acc[i][6] + bv[6], acc[i][7] + bv[7]);
        *(float4*)(crow)     = v0;
        *(float4*)(crow + 4) = v1;
    }
}

// ==============================================================================
// Wavefront kernel: all 3 layers concurrently.
//   layer 0:  h_t = tanh( g_P[b][t] + W_hh0 h_{t-1} + b_hh0 )
//   layer l:  h_t = tanh( W_ih h^{l-1}_t + b_ih + W_hh h_{t-1} + b_hh )
// Grid (32, 3): blockIdx.y = layer; blockIdx.x: g = x>>3 (batch group), jg = x&7.
// Warp w owns k-chunk [64w, 64w+64) of both the recurrent and the input dot.
// W_hh slice in registers (f32x2 pairs); W_ih slice streamed from L2.
// h exchanged via 4-slot global ring + monotonic flags (per producer CTA).
// ==============================================================================
__global__ __launch_bounds__(256, 1) void wave_kernel(
    const float* __restrict__ w_ihs,   // [2][512][512] (layers 1,2)
    const float* __restrict__ w_hhs,   // [3][512][512]
    const float* __restrict__ h0,      // [3][32][512]
    const float* __restrict__ b_ihs,   // [3][512]
    const float* __restrict__ b_hhs,   // [3][512]
    float* __restrict__ hidden,        // [3][32][512]
    float* __restrict__ outseq)        // [32][1024][512]
{
    const int l  = blockIdx.y;            // layer
    const int g  = blockIdx.x >> 3;       // batch group
    const int jg = blockIdx.x & 7;        // j-CTA
    const int b0 = g * NB;
    const int jbase = jg * 64;

    const int tid  = threadIdx.x;
    const int w    = tid >> 5;            // warp -> k-chunk / producer peer
    const int lane = tid & 31;

    __shared__ __align__(16) float sh_own[NB][HID];     // 16 KB (warp-private cols)
    __shared__ __align__(16) float sh_low[NB][HID];     // 16 KB
    __shared__ float sh_red[8][NB][64];                 // 16 KB  [w][b][j]

    // ---- W_hh slice into registers, f32x2-packed along k ----
    unsigned long long Wr0[32], Wr1[32];
    {
        const float* Whh = w_hhs + (size_t)l * HID * HID;
        const float4* r0 = (const float4*)(Whh + (size_t)(jbase + lane) * HID + w * 64);
        const float4* r1 = (const float4*)(Whh + (size_t)(jbase + lane + 32) * HID + w * 64);
        #pragma unroll
        for (int i = 0; i < 16; i++) {
            float4 v0 = r0[i];
            Wr0[2 * i]     = pack2(v0.x, v0.y);
            Wr0[2 * i + 1] = pack2(v0.z, v0.w);
            float4 v1 = r1[i];
            Wr1[2 * i]     = pack2(v1.x, v1.y);
            Wr1[2 * i + 1] = pack2(v1.z, v1.w);
        }
    }

    // W_ih row pointers for this lane (layers 1,2), streamed from L2 each step
    const float* wi0p = nullptr;
    const float* wi1p = nullptr;
    if (l > 0) {
        const float* Wih = w_ihs + (size_t)(l - 1) * HID * HID;
        wi0p = Wih + (size_t)(jbase + lane) * HID + w * 64;
        wi1p = Wih + (size_t)(jbase + lane + 32) * HID + w * 64;
    }

    // Flag addresses
    int* flag_base   = g_flag;
    int* my_flag     = &flag_base[(l * NGRP + g) * GJ + jg];
    const int* own_f = &flag_base[(l * NGRP + g) * GJ + w];          // same layer, peer w
    const int* low_f = (l > 0) ? &flag_base[((l - 1) * NGRP + g) * GJ + w] : nullptr;
    const int* dn_f  = (l < 2 && tid < GJ)
                     ? &flag_base[((l + 1) * NGRP + g) * GJ + tid] : nullptr;

    // Reduce-phase mapping: thread -> outputs (b, j) and (b+4, j)
    const int rb = tid >> 6;              // 0..3
    const int rj = tid & 63;
    float bias_r;
    if (l == 0) bias_r = b_hhs[jbase + rj];
    else        bias_r = b_ihs[(size_t)l * HID + jbase + rj] +
                         b_hhs[(size_t)l * HID + jbase + rj];
    const float* pre0 = g_P + ((size_t)(b0 + rb)     * SEQ) * HID + jbase + rj;
    const float* pre1 = g_P + ((size_t)(b0 + rb + 4) * SEQ) * HID + jbase + rj;

    // ring base helpers (flattened indexing of g_hring[l][slot][b][k])
    float* ring = &g_hring[0][0][0][0];

    for (int t = 0; t < SEQ; t++) {
        // Layer-0 pre-activation prefetch (DRAM latency hidden by the step)
        float p0 = 0.f, p1 = 0.f;
        if (l == 0) {
            p0 = ldg_nc_f32(pre0 + (size_t)t * HID);
            p1 = ldg_nc_f32(pre1 + (size_t)t * HID);
        }

        // ---- acquire own h_{t-1} chunk (warp-private) ----
        {
            if (t > 0) {
                if (lane == 0) while (ld_acquire_gpu(own_f) < t) { }
                __syncwarp();
            }
            const float* src = (t == 0)
                ? h0 + ((size_t)(l * BATCH + b0)) * HID
                : ring + (((size_t)(l * 4 + ((t - 1) & 3)) * BATCH + b0)) * HID;
            #pragma unroll
            for (int r = 0; r < 4; r++) {
                int e = r * 32 + lane;
                int b = e >> 4, q = (e & 15) * 4;
                float4 v = ldg_f32x4(src + (size_t)b * HID + w * 64 + q);
                *(float4*)&sh_own[b][w * 64 + q] = v;
            }
        }

        // ---- acquire lower-layer h_t chunk (layers 1,2) ----
        if (l > 0) {
            if (lane == 0) while (ld_acquire_gpu(low_f) < t + 1) { }
            __syncwarp();
            const float* src = ring + (((size_t)((l - 1) * 4 + (t & 3)) * BATCH + b0)) * HID;
            #pragma unroll
            for (int r = 0; r < 4; r++) {
                int e = r * 32 + lane;
                int b = e >> 4, q = (e & 15) * 4;
                float4 v = ldg_f32x4(src + (size_t)b * HID + w * 64 + q);
                *(float4*)&sh_low[b][w * 64 + q] = v;
            }
        }
        __syncwarp();

        // ---- dot products ----
        unsigned long long accA[NB], accB[NB];
        #pragma unroll
        for (int b = 0; b < NB; b++) { accA[b] = 0ull; accB[b] = 0ull; }

        if (l > 0) {   // input projection on the fly: W_ih slice from L2
            #pragma unroll
            for (int q = 0; q < 16; q++) {
                ulonglong2 w0 = ldg_nc_u64x2(wi0p + 4 * q);
                ulonglong2 w1 = ldg_nc_u64x2(wi1p + 4 * q);
                #pragma unroll
                for (int b = 0; b < NB; b++) {
                    ulonglong2 h2 = *(const ulonglong2*)&sh_low[b][w * 64 + 4 * q];
                    accA[b] = ffma2(w0.x, h2.x, accA[b]);
                    accA[b] = ffma2(w0.y, h2.y, accA[b]);
                    accB[b] = ffma2(w1.x, h2.x, accB[b]);
                    accB[b] = ffma2(w1.y, h2.y, accB[b]);
                }
            }
        }
        // recurrent part: W_hh in registers
        #pragma unroll
        for (int q = 0; q < 16; q++) {
            #pragma unroll
            for (int b = 0; b < NB; b++) {
                ulonglong2 h2 = *(const ulonglong2*)&sh_own[b][w * 64 + 4 * q];
                accA[b] = ffma2(Wr0[2 * q],     h2.x, accA[b]);
                accA[b] = ffma2(Wr0[2 * q + 1], h2.y, accA[b]);
                accB[b] = ffma2(Wr1[2 * q],     h2.x, accB[b]);
                accB[b] = ffma2(Wr1[2 * q + 1], h2.y, accB[b]);
            }
        }
        #pragma unroll
        for (int b = 0; b < NB; b++) {
            sh_red[w][b][lane]      = pairsum(accA[b]);
            sh_red[w][b][lane + 32] = pairsum(accB[b]);
        }

        // ---- downstream credit (slot t&3 holds h(t-4); layer l+1 must be done) ----
        if (dn_f && t >= 4) {
            while (ld_acquire_gpu(dn_f) < t - 3) { }
        }
        __syncthreads();

        // ---- reduce, tanh, publish (each thread: outputs (rb,rj) and (rb+4,rj)) ----
        {
            float s0 = bias_r, s1 = bias_r;
            #pragma unroll
            for (int ww = 0; ww < 8; ww++) {
                s0 += sh_red[ww][rb][rj];
                s1 += sh_red[ww][rb + 4][rj];
            }
            if (l == 0) { s0 += p0; s1 += p1; }
            float v0 = tanhf(s0);
            float v1 = tanhf(s1);

            float* dst = ring + (((size_t)(l * 4 + (t & 3)) * BATCH + b0)) * HID;
            dst[(size_t)rb * HID + jbase + rj]       = v0;
            dst[(size_t)(rb + 4) * HID + jbase + rj] = v1;

            if (l == 2) {
                outseq[((size_t)(b0 + rb) * SEQ + t) * HID + jbase + rj]     = v0;
                outseq[((size_t)(b0 + rb + 4) * SEQ + t) * HID + jbase + rj] = v1;
            }
            if (t == SEQ - 1) {
                hidden[((size_t)l * BATCH + b0 + rb) * HID + jbase + rj]     = v0;
                hidden[((size_t)l * BATCH + b0 + rb + 4) * HID + jbase + rj] = v1;
            }
        }
        __syncthreads();

        if (tid == 0) {
            __threadfence();
            st_relaxed_gpu(my_flag, t + 1);
        }
    }
}

// ==============================================================================
extern "C" void kernel_launch(void* const* d_in, const int* in_sizes, int n_in,
                              void* d_out, int out_size)
{
    const float* x     = (const float*)d_in[0];   // [32,1024,128]
    const float* h0    = (const float*)d_in[1];   // [3,32,512]
    const float* w_ih0 = (const float*)d_in[2];   // [512,128]
    const float* w_ihs = (const float*)d_in[3];   // [2,512,512]
    const float* w_hhs = (const float*)d_in[4];   // [3,512,512]
    const float* b_ihs = (const float*)d_in[5];   // [3,512]
    const float* b_hhs = (const float*)d_in[6];   // [3,512]

    float* out    = (float*)d_out;
    float* hidden = out;                                   // [3][32][512]
    float* outseq = out + (size_t)LAYERS * BATCH * HID;    // [32*1024][512]

    // Layer-0 input projection (also resets wavefront flags, stream-ordered)
    dim3 pg(HID / 128, (BATCH * SEQ) / 128);               // (4, 256)
    proj_kernel<<<pg, 256>>>(x, w_ih0, b_ihs, INDIM);

    // Wavefront over all 3 layers
    dim3 wg(NGRP * GJ, LAYERS);                            // (32, 3) = 96 CTAs
    wave_kernel<<<wg, 256>>>(w_ihs, w_hhs, h0, b_ihs, b_hhs, hidden, outseq);
}